// round 14
// baseline (speedup 1.0000x reference)
#include <cuda_runtime.h>
#include <cuda_bf16.h>

typedef unsigned int u32;
typedef unsigned short u16;
typedef unsigned long long u64;

#define BATCH 64
#define SEQ   1024
#define DM    128
#define DEVINL __device__ __forceinline__

// bf16 hi/lo split scratch, packed pairs as u32 (low half = even index)
__device__ u32 g_q_hi[BATCH*SEQ*64];
__device__ u32 g_q_lo[BATCH*SEQ*64];
__device__ u32 g_k_hi[BATCH*SEQ*64];
__device__ u32 g_k_lo[BATCH*SEQ*64];
__device__ u32 g_vt_hi[BATCH*DM*512];   // [b][h][j/2]
__device__ u32 g_vt_lo[BATCH*DM*512];

// ---------------- helpers ----------------
DEVINL float tanh_fast(float x){
    float ax = fminf(fabsf(x), 20.0f);
    float e  = __expf(2.0f*ax);
    return copysignf(__fdividef(e-1.0f, e+1.0f), x);
}
DEVINL u32 bfpair(float e0, float e1){ u32 r; asm("cvt.rn.bf16x2.f32 %0, %1, %2;":"=r"(r):"f"(e1),"f"(e0)); return r; }
DEVINL float bflo_f(u32 p){ return __uint_as_float(p<<16); }
DEVINL float bfhi_f(u32 p){ return __uint_as_float(p & 0xFFFF0000u); }
DEVINL void split2(float e0, float e1, u32 &hi, u32 &lo){
    hi = bfpair(e0, e1);
    lo = bfpair(e0 - bflo_f(hi), e1 - bfhi_f(hi));
}
DEVINL void mma16816(float* c, u32 a0,u32 a1,u32 a2,u32 a3, u32 b0,u32 b1){
    asm volatile("mma.sync.aligned.m16n8k16.row.col.f32.bf16.bf16.f32 "
        "{%0,%1,%2,%3}, {%4,%5,%6,%7}, {%8,%9}, {%0,%1,%2,%3};"
        : "+f"(c[0]),"+f"(c[1]),"+f"(c[2]),"+f"(c[3])
        : "r"(a0),"r"(a1),"r"(a2),"r"(a3),"r"(b0),"r"(b1));
}
DEVINL u32 sm_u32(const void* p){ u32 a; asm("{ .reg .u64 t; cvta.to.shared.u64 t, %1; cvt.u32.u64 %0, t; }":"=r"(a):"l"(p)); return a; }
DEVINL void cp16(u32 dst, const void* src){
    asm volatile("cp.async.cg.shared.global [%0], [%1], 16;"::"r"(dst),"l"(src):"memory");
}
#define CP_COMMIT() asm volatile("cp.async.commit_group;":::"memory")
#define CP_WAIT1()  asm volatile("cp.async.wait_group 1;":::"memory")
#define CP_WAIT0()  asm volatile("cp.async.wait_group 0;":::"memory")

// =====================================================================
// Fused tensorized projections: one CTA = 128 rows; x fragments split
// once in registers, reused for Wq, Wk, Wv. MMA loops: ks-outer,
// 4-group term-major (accumulator chain spacing >= 4).
// =====================================================================
#define PW_STRIDE 68      // u32
#define PW_HI     0
#define PW_LO     8704
#define P_SMEM_BYTES (17408*4)   // 69,632 (y_s transpose scratch: 128*130*4=66,560)

__global__ void __launch_bounds__(256, 1)
proj_tc_kernel(const float* __restrict__ x,
               const float* __restrict__ Wq, const float* __restrict__ bq,
               const float* __restrict__ Wk, const float* __restrict__ bk,
               const float* __restrict__ Wv, const float* __restrict__ bv)
{
    extern __shared__ char smc[];
    u32* ws_hi = (u32*)smc + PW_HI;
    u32* ws_lo = (u32*)smc + PW_LO;

    int tid = threadIdx.x, wid = tid>>5, lane = tid&31;
    int g = lane>>2, tig = lane&3;
    int r0 = blockIdx.x * 128;
    int b  = r0 >> 10;
    int rowg = wid*16 + g;
    long grow0 = (long)(r0 + rowg);

    // ---- x fragments: rows rowg, rowg+8; split in registers, persist ----
    u32 axh[2][16], axl[2][16];
    #pragma unroll
    for (int r2=0;r2<2;++r2){
        const float* xr = x + (grow0 + 8*r2)*DM;
        #pragma unroll
        for (int t=0;t<16;++t){
            float2 v = __ldg((const float2*)(xr + 8*t + 2*tig));
            split2(v.x, v.y, axh[r2][t], axl[r2][t]);
        }
    }

    #pragma unroll 1
    for (int sel=0; sel<3; ++sel){
        const float* W    = (sel==0)? Wq : (sel==1)? Wk : Wv;
        const float* bias = (sel==0)? bq : (sel==1)? bk : bv;

        __syncthreads();   // prior sel done reading ws
        #pragma unroll
        for (int p=0;p<16;++p){
            int i = tid + p*256, row = i>>5, c4 = (i&31)*4;
            float4 wv = __ldg((const float4*)(W + (long)row*DM + c4));
            u32 h0,l0,h1,l1;
            split2(wv.x, wv.y, h0, l0);
            split2(wv.z, wv.w, h1, l1);
            *(u64*)(ws_hi + row*PW_STRIDE + (c4>>1)) = ((u64)h1<<32)|h0;
            *(u64*)(ws_lo + row*PW_STRIDE + (c4>>1)) = ((u64)l1<<32)|l0;
        }
        __syncthreads();

        float oc[16][4];
        #pragma unroll
        for (int n=0;n<16;++n){ oc[n][0]=0; oc[n][1]=0; oc[n][2]=0; oc[n][3]=0; }
        #pragma unroll
        for (int ks=0;ks<8;++ks){
            u32 a0h=axh[0][2*ks], a1h=axh[1][2*ks], a2h=axh[0][2*ks+1], a3h=axh[1][2*ks+1];
            u32 a0l=axl[0][2*ks], a1l=axl[1][2*ks], a2l=axl[0][2*ks+1], a3l=axl[1][2*ks+1];
            #pragma unroll
            for (int n4=0;n4<4;++n4){
                u32 bh0[4],bh1[4],bl0[4],bl1[4];
                #pragma unroll
                for (int j=0;j<4;++j){
                    int h = 8*(4*n4+j) + g;
                    bh0[j] = ws_hi[h*PW_STRIDE + 8*ks + tig];
                    bh1[j] = ws_hi[h*PW_STRIDE + 8*ks + 4 + tig];
                    bl0[j] = ws_lo[h*PW_STRIDE + 8*ks + tig];
                    bl1[j] = ws_lo[h*PW_STRIDE + 8*ks + 4 + tig];
                }
                #pragma unroll
                for (int j=0;j<4;++j) mma16816(oc[4*n4+j], a0h,a1h,a2h,a3h, bh0[j], bh1[j]);
                #pragma unroll
                for (int j=0;j<4;++j) mma16816(oc[4*n4+j], a0h,a1h,a2h,a3h, bl0[j], bl1[j]);
                #pragma unroll
                for (int j=0;j<4;++j) mma16816(oc[4*n4+j], a0l,a1l,a2l,a3l, bh0[j], bh1[j]);
            }
        }

        if (sel < 2){
            u32* gh = (sel==0)? g_q_hi : g_k_hi;
            u32* gl = (sel==0)? g_q_lo : g_k_lo;
            #pragma unroll
            for (int n=0;n<16;++n){
                float2 b2 = __ldg((const float2*)(bias + 8*n + 2*tig));
                float y0 = tanh_fast(oc[n][0] + b2.x);
                float y1 = tanh_fast(oc[n][1] + b2.y);
                float y2 = tanh_fast(oc[n][2] + b2.x);
                float y3 = tanh_fast(oc[n][3] + b2.y);
                u32 h2,l2;
                split2(y0,y1,h2,l2);
                gh[grow0*64 + 4*n + tig] = h2;  gl[grow0*64 + 4*n + tig] = l2;
                split2(y2,y3,h2,l2);
                gh[(grow0+8)*64 + 4*n + tig] = h2;  gl[(grow0+8)*64 + 4*n + tig] = l2;
            }
        } else {
            // V: transpose through smem -> g_vt[b][h][j/2]
            __syncthreads();   // all warps done reading ws (about to overwrite)
            float* y_s = (float*)smc;    // [h][row], stride 130
            #pragma unroll
            for (int n=0;n<16;++n){
                float2 b2 = __ldg((const float2*)(bias + 8*n + 2*tig));
                int col = 8*n + 2*tig;
                y_s[(col  )*130 + rowg    ] = tanh_fast(oc[n][0] + b2.x);
                y_s[(col+1)*130 + rowg    ] = tanh_fast(oc[n][1] + b2.y);
                y_s[(col  )*130 + rowg + 8] = tanh_fast(oc[n][2] + b2.x);
                y_s[(col+1)*130 + rowg + 8] = tanh_fast(oc[n][3] + b2.y);
            }
            __syncthreads();
            int h = tid >> 1;
            int phalf = (tid & 1) * 32;
            long gbase = ((long)(b*DM + h))*512 + ((r0 & 1023) >> 1) + phalf;
            #pragma unroll
            for (int ck=0; ck<8; ++ck){
                u32 hw[4], lw[4];
                #pragma unroll
                for (int q2=0;q2<4;++q2){
                    int p2 = phalf + ck*4 + q2;
                    float2 yy = *(const float2*)(y_s + h*130 + 2*p2);
                    split2(yy.x, yy.y, hw[q2], lw[q2]);
                }
                *(uint4*)(g_vt_hi + gbase + ck*4) = make_uint4(hw[0],hw[1],hw[2],hw[3]);
                *(uint4*)(g_vt_lo + gbase + ck*4) = make_uint4(lw[0],lw[1],lw[2],lw[3]);
            }
        }
    }
}

// =====================================================================
// Attention (R11 structure: 8 warps, cp.async double buffer) with MMA
// loops re-ordered for accumulator chain spacing >= 4.
// =====================================================================
#define KS_STRIDE 68
#define VT_STRIDE 36
#define OF_KH 0
#define OF_KL 4352
#define OF_VH 8704
#define OF_VL 13312
#define OF_MS 17920
#define BUF_U32 26624
#define A_SMEM (2*BUF_U32*4)   // 212,992 B

__global__ void __launch_bounds__(256, 1)
attn_kernel(const int* __restrict__ mask, float* __restrict__ out)
{
    extern __shared__ char smc[];
    u32* smp = (u32*)smc;
    u32  sb  = sm_u32(smc);

    int tid = threadIdx.x, wid = tid>>5, lane = tid&31;
    int g = lane>>2, tig = lane&3;
    int b  = blockIdx.y;
    int q0 = blockIdx.x * 128;
    int rowg  = wid*16 + g;
    long grow0 = (long)(b*SEQ + q0 + rowg);

    const uint4* gk_h = (const uint4*)(g_k_hi + (long)(b*SEQ)*64);
    const uint4* gk_l = (const uint4*)(g_k_lo + (long)(b*SEQ)*64);
    const uint4* gv_h = (const uint4*)(g_vt_hi + (long)(b*DM)*512);
    const uint4* gv_l = (const uint4*)(g_vt_lo + (long)(b*DM)*512);
    const int*   mg   = mask + ((long)(b*SEQ + q0))*SEQ;

    // ---- Q fragments (persist): rows rowg, rowg+8 ----
    u32 aqh[2][16], aql[2][16];
    {
        const u32* qh0 = g_q_hi + grow0*64;
        const u32* ql0 = g_q_lo + grow0*64;
        #pragma unroll
        for (int t=0;t<16;++t){
            int c = 4*t + tig;
            aqh[0][t] = __ldg(&qh0[c]);  aqh[1][t] = __ldg(&qh0[8*64 + c]);
            aql[0][t] = __ldg(&ql0[c]);  aql[1][t] = __ldg(&ql0[8*64 + c]);
        }
    }

    auto stage = [&](int jb, int bi){
        u32 base = sb + (u32)(bi*BUF_U32*4);
        int j0 = jb*64;
        #pragma unroll
        for (int p=0;p<4;++p){                 // K: 64 rows x 16 uint4 (hi+lo)
            int i = tid + p*256, row = i>>4, c4 = (i&15)*4;
            int gi = j0*16 + i;
            cp16(base + (OF_KH + row*KS_STRIDE + c4)*4, gk_h + gi);
            cp16(base + (OF_KL + row*KS_STRIDE + c4)*4, gk_l + gi);
        }
        #pragma unroll
        for (int p=0;p<4;++p){                 // V^T: 128 rows x 8 uint4 (hi+lo)
            int i = tid + p*256, row = i>>3, c4 = (i&7)*4;
            int src = row*128 + (j0>>3) + (c4>>2);
            cp16(base + (OF_VH + row*VT_STRIDE + c4)*4, gv_h + src);
            cp16(base + (OF_VL + row*VT_STRIDE + c4)*4, gv_l + src);
        }
        #pragma unroll
        for (int p=0;p<8;++p){                 // mask raw: 128 rows x 16 uint4
            int i = tid + p*256, row = i>>4, c16 = (i&15);
            cp16(base + (OF_MS + row*KS_STRIDE + c16*4)*4,
                 (const uint4*)(mg + (long)row*SEQ + j0) + c16);
        }
    };

    float oc[16][4];
    #pragma unroll
    for (int n=0;n<16;++n){ oc[n][0]=0; oc[n][1]=0; oc[n][2]=0; oc[n][3]=0; }
    float rs0 = 0.0f, rs1 = 0.0f;

    stage(0, 0); CP_COMMIT();

    for (int jb = 0; jb < 16; ++jb) {
        __syncthreads();
        if (jb < 15) { stage(jb+1, (jb+1)&1); CP_COMMIT(); CP_WAIT1(); }
        else         { CP_WAIT0(); }
        __syncthreads();

        u32* bp    = smp + (jb&1)*BUF_U32;
        u32* ks_hi = bp + OF_KH;
        u32* ks_lo = bp + OF_KL;
        u32* vs_hi = bp + OF_VH;
        u32* vs_lo = bp + OF_VL;
        const int* msB = (const int*)(bp + OF_MS);

        // ---- QK: ks-outer, 4-group term-major (chain spacing 4) ----
        float sc[8][4];
        #pragma unroll
        for (int n=0;n<8;++n){ sc[n][0]=0; sc[n][1]=0; sc[n][2]=0; sc[n][3]=0; }
        #pragma unroll
        for (int ks=0;ks<8;++ks){
            u32 a0h=aqh[0][2*ks], a1h=aqh[1][2*ks], a2h=aqh[0][2*ks+1], a3h=aqh[1][2*ks+1];
            u32 a0l=aql[0][2*ks], a1l=aql[1][2*ks], a2l=aql[0][2*ks+1], a3l=aql[1][2*ks+1];
            #pragma unroll
            for (int n4=0;n4<2;++n4){
                u32 bh0[4],bh1[4],bl0[4],bl1[4];
                #pragma unroll
                for (int j=0;j<4;++j){
                    int key = 8*(4*n4+j) + g;
                    bh0[j] = ks_hi[key*KS_STRIDE + 8*ks + tig];
                    bh1[j] = ks_hi[key*KS_STRIDE + 8*ks + 4 + tig];
                    bl0[j] = ks_lo[key*KS_STRIDE + 8*ks + tig];
                    bl1[j] = ks_lo[key*KS_STRIDE + 8*ks + 4 + tig];
                }
                #pragma unroll
                for (int j=0;j<4;++j) mma16816(sc[4*n4+j], a0h,a1h,a2h,a3h, bh0[j], bh1[j]);
                #pragma unroll
                for (int j=0;j<4;++j) mma16816(sc[4*n4+j], a0h,a1h,a2h,a3h, bl0[j], bl1[j]);
                #pragma unroll
                for (int j=0;j<4;++j) mma16816(sc[4*n4+j], a0l,a1l,a2l,a3l, bh0[j], bh1[j]);
            }
        }

        // ---- mask + exp ----
        const int* mrow0 = msB + rowg*KS_STRIDE;
        const int* mrow1 = mrow0 + 8*KS_STRIDE;
        #pragma unroll
        for (int n=0;n<8;++n){
            int col = 8*n + 2*tig;
            int2 ma  = *(const int2*)(mrow0 + col);
            int2 mb2 = *(const int2*)(mrow1 + col);
            float p0 = ma.x  ? __expf(sc[n][0]) : 0.0f;
            float p1 = ma.y  ? __expf(sc[n][1]) : 0.0f;
            float p2 = mb2.x ? __expf(sc[n][2]) : 0.0f;
            float p3 = mb2.y ? __expf(sc[n][3]) : 0.0f;
            rs0 += p0 + p1;  rs1 += p2 + p3;
            sc[n][0]=p0; sc[n][1]=p1; sc[n][2]=p2; sc[n][3]=p3;
        }

        // ---- PV: ks-outer, 4-group term-major ----
        #pragma unroll
        for (int ks=0;ks<4;++ks){
            u32 ah[4], al[4];
            split2(sc[2*ks  ][0], sc[2*ks  ][1], ah[0], al[0]);
            split2(sc[2*ks  ][2], sc[2*ks  ][3], ah[1], al[1]);
            split2(sc[2*ks+1][0], sc[2*ks+1][1], ah[2], al[2]);
            split2(sc[2*ks+1][2], sc[2*ks+1][3], ah[3], al[3]);
            #pragma unroll
            for (int n4=0;n4<4;++n4){
                u32 bh0[4],bh1[4],bl0[4],bl1[4];
                #pragma unroll
                for (int j=0;j<4;++j){
                    int h = 8*(4*n4+j) + g;
                    bh0[j] = vs_hi[h*VT_STRIDE + 8*ks + tig];
                    bh1[j] = vs_hi[h*VT_STRIDE + 8*ks + 4 + tig];
                    bl0[j] = vs_lo[h*VT_STRIDE + 8*ks + tig];
                    bl1[j] = vs_lo[h*VT_STRIDE + 8*ks + 4 + tig];
                }
                #pragma unroll
                for (int j=0;j<4;++j) mma16816(oc[4*n4+j], ah[0],ah[1],ah[2],ah[3], bh0[j], bh1[j]);
                #pragma unroll
                for (int j=0;j<4;++j) mma16816(oc[4*n4+j], ah[0],ah[1],ah[2],ah[3], bl0[j], bl1[j]);
                #pragma unroll
                for (int j=0;j<4;++j) mma16816(oc[4*n4+j], al[0],al[1],al[2],al[3], bh0[j], bh1[j]);
            }
        }
    }

    // ---- row sums (quad reduce) + normalize + store ----
    rs0 += __shfl_xor_sync(0xFFFFFFFFu, rs0, 1);
    rs0 += __shfl_xor_sync(0xFFFFFFFFu, rs0, 2);
    rs1 += __shfl_xor_sync(0xFFFFFFFFu, rs1, 1);
    rs1 += __shfl_xor_sync(0xFFFFFFFFu, rs1, 2);
    float inv0 = __fdividef(1.0f, rs0);
    float inv1 = __fdividef(1.0f, rs1);

    float* o0 = out + grow0*DM;
    float* o1 = o0 + 8*DM;
    #pragma unroll
    for (int n=0;n<16;++n){
        int col = 8*n + 2*tig;
        *(float2*)(o0 + col) = make_float2(oc[n][0]*inv0, oc[n][1]*inv0);
        *(float2*)(o1 + col) = make_float2(oc[n][2]*inv1, oc[n][3]*inv1);
    }
}

// =====================================================================
extern "C" void kernel_launch(void* const* d_in, const int* in_sizes, int n_in,
                              void* d_out, int out_size)
{
    const float* x    = (const float*)d_in[0];
    const int*   mask = (const int*)  d_in[1];
    const float* Wv   = (const float*)d_in[2];
    const float* bv   = (const float*)d_in[3];
    const float* Wk   = (const float*)d_in[4];
    const float* bk   = (const float*)d_in[5];
    const float* Wq   = (const float*)d_in[6];
    const float* bq   = (const float*)d_in[7];
    float* out = (float*)d_out;

    cudaFuncSetAttribute(proj_tc_kernel, cudaFuncAttributeMaxDynamicSharedMemorySize, P_SMEM_BYTES);
    cudaFuncSetAttribute(attn_kernel,    cudaFuncAttributeMaxDynamicSharedMemorySize, A_SMEM);

    proj_tc_kernel<<<512, 256, P_SMEM_BYTES>>>(x, Wq, bq, Wk, bk, Wv, bv);
    attn_kernel<<<dim3(SEQ/128, BATCH), 256, A_SMEM>>>(mask, out);
}

// round 15
// speedup vs baseline: 1.6089x; 1.6089x over previous
#include <cuda_runtime.h>
#include <cuda_bf16.h>

typedef unsigned int u32;
typedef unsigned short u16;
typedef unsigned long long u64;

#define BATCH 64
#define SEQ   1024
#define DM    128
#define DEVINL __device__ __forceinline__

// bf16 hi/lo split scratch, packed pairs as u32.
// Q : [row][4n+tig]                (R11 order)
// K : [row][pair-interleaved]      (pos 8g+2t   -> pair 8g+t,
//                                   pos 8g+2t+1 -> pair 8g+4+t)
// VT: [b][h][pair-interleaved]     (same 8-group interleave)
__device__ u32 g_q_hi[BATCH*SEQ*64];
__device__ u32 g_q_lo[BATCH*SEQ*64];
__device__ u32 g_k_hi[BATCH*SEQ*64];
__device__ u32 g_k_lo[BATCH*SEQ*64];
__device__ u32 g_vt_hi[BATCH*DM*512];   // [b][h][j/2]
__device__ u32 g_vt_lo[BATCH*DM*512];

// ---------------- helpers ----------------
DEVINL float tanh_fast(float x){
    float ax = fminf(fabsf(x), 20.0f);
    float e  = __expf(2.0f*ax);
    return copysignf(__fdividef(e-1.0f, e+1.0f), x);
}
DEVINL u32 bfpair(float e0, float e1){ u32 r; asm("cvt.rn.bf16x2.f32 %0, %1, %2;":"=r"(r):"f"(e1),"f"(e0)); return r; }
DEVINL float bflo_f(u32 p){ return __uint_as_float(p<<16); }
DEVINL float bfhi_f(u32 p){ return __uint_as_float(p & 0xFFFF0000u); }
DEVINL void split2(float e0, float e1, u32 &hi, u32 &lo){
    hi = bfpair(e0, e1);
    lo = bfpair(e0 - bflo_f(hi), e1 - bfhi_f(hi));
}
DEVINL void mma16816(float* c, u32 a0,u32 a1,u32 a2,u32 a3, u32 b0,u32 b1){
    asm volatile("mma.sync.aligned.m16n8k16.row.col.f32.bf16.bf16.f32 "
        "{%0,%1,%2,%3}, {%4,%5,%6,%7}, {%8,%9}, {%0,%1,%2,%3};"
        : "+f"(c[0]),"+f"(c[1]),"+f"(c[2]),"+f"(c[3])
        : "r"(a0),"r"(a1),"r"(a2),"r"(a3),"r"(b0),"r"(b1));
}
DEVINL u32 sm_u32(const void* p){ u32 a; asm("{ .reg .u64 t; cvta.to.shared.u64 t, %1; cvt.u32.u64 %0, t; }":"=r"(a):"l"(p)); return a; }
DEVINL void cp16(u32 dst, const void* src){
    asm volatile("cp.async.cg.shared.global [%0], [%1], 16;"::"r"(dst),"l"(src):"memory");
}
#define CP_COMMIT() asm volatile("cp.async.commit_group;":::"memory")
#define CP_WAIT1()  asm volatile("cp.async.wait_group 1;":::"memory")
#define CP_WAIT0()  asm volatile("cp.async.wait_group 0;":::"memory")

// =====================================================================
// Fused tensorized projections (R11 MMA core; K/VT writers emit the
// pair-interleaved layouts so attention can LDS.64 B-fragments).
// =====================================================================
#define PW_STRIDE 68      // u32
#define PW_HI     0
#define PW_LO     8704
#define P_SMEM_BYTES (17408*4)   // 69,632 (y_s transpose scratch: 128*130*4=66,560)

__global__ void __launch_bounds__(256, 1)
proj_tc_kernel(const float* __restrict__ x,
               const float* __restrict__ Wq, const float* __restrict__ bq,
               const float* __restrict__ Wk, const float* __restrict__ bk,
               const float* __restrict__ Wv, const float* __restrict__ bv)
{
    extern __shared__ char smc[];
    u32* ws_hi = (u32*)smc + PW_HI;
    u32* ws_lo = (u32*)smc + PW_LO;

    int tid = threadIdx.x, wid = tid>>5, lane = tid&31;
    int g = lane>>2, tig = lane&3;
    int r0 = blockIdx.x * 128;
    int b  = r0 >> 10;
    int rowg = wid*16 + g;
    long grow0 = (long)(r0 + rowg);

    // ---- x fragments: rows rowg, rowg+8; split once, persist ----
    u32 axh[2][16], axl[2][16];
    #pragma unroll
    for (int r2=0;r2<2;++r2){
        const float* xr = x + (grow0 + 8*r2)*DM;
        #pragma unroll
        for (int t=0;t<16;++t){
            float2 v = __ldg((const float2*)(xr + 8*t + 2*tig));
            split2(v.x, v.y, axh[r2][t], axl[r2][t]);
        }
    }

    #pragma unroll 1
    for (int sel=0; sel<3; ++sel){
        const float* W    = (sel==0)? Wq : (sel==1)? Wk : Wv;
        const float* bias = (sel==0)? bq : (sel==1)? bk : bv;

        __syncthreads();   // prior sel done reading ws
        #pragma unroll
        for (int p=0;p<16;++p){
            int i = tid + p*256, row = i>>5, c4 = (i&31)*4;
            float4 wv = __ldg((const float4*)(W + (long)row*DM + c4));
            u32 h0,l0,h1,l1;
            split2(wv.x, wv.y, h0, l0);
            split2(wv.z, wv.w, h1, l1);
            *(u64*)(ws_hi + row*PW_STRIDE + (c4>>1)) = ((u64)h1<<32)|h0;
            *(u64*)(ws_lo + row*PW_STRIDE + (c4>>1)) = ((u64)l1<<32)|l0;
        }
        __syncthreads();

        float oc[16][4];
        #pragma unroll
        for (int n=0;n<16;++n){ oc[n][0]=0; oc[n][1]=0; oc[n][2]=0; oc[n][3]=0; }
        #pragma unroll
        for (int n=0;n<16;++n){
            int h = 8*n + g;
            #pragma unroll
            for (int ks=0;ks<8;++ks){
                u32 bh0 = ws_hi[h*PW_STRIDE + 8*ks + tig];
                u32 bh1 = ws_hi[h*PW_STRIDE + 8*ks + 4 + tig];
                u32 bl0 = ws_lo[h*PW_STRIDE + 8*ks + tig];
                u32 bl1 = ws_lo[h*PW_STRIDE + 8*ks + 4 + tig];
                mma16816(oc[n], axh[0][2*ks], axh[1][2*ks], axh[0][2*ks+1], axh[1][2*ks+1], bh0, bh1);
                mma16816(oc[n], axh[0][2*ks], axh[1][2*ks], axh[0][2*ks+1], axh[1][2*ks+1], bl0, bl1);
                mma16816(oc[n], axl[0][2*ks], axl[1][2*ks], axl[0][2*ks+1], axl[1][2*ks+1], bh0, bh1);
            }
        }

        if (sel == 0){
            // Q (R11 order): pair p=4n+tig at col 4n+tig
            #pragma unroll
            for (int n=0;n<16;++n){
                float2 b2 = __ldg((const float2*)(bias + 8*n + 2*tig));
                float y0 = tanh_fast(oc[n][0] + b2.x);
                float y1 = tanh_fast(oc[n][1] + b2.y);
                float y2 = tanh_fast(oc[n][2] + b2.x);
                float y3 = tanh_fast(oc[n][3] + b2.y);
                u32 h2,l2;
                split2(y0,y1,h2,l2);
                g_q_hi[grow0*64 + 4*n + tig] = h2;  g_q_lo[grow0*64 + 4*n + tig] = l2;
                split2(y2,y3,h2,l2);
                g_q_hi[(grow0+8)*64 + 4*n + tig] = h2;  g_q_lo[(grow0+8)*64 + 4*n + tig] = l2;
            }
        } else if (sel == 1){
            // K pair-interleaved (verified in R12): pos 8gk+2tig <- pair 8gk+tig,
            // pos 8gk+2tig+1 <- pair 8gk+4+tig
            u32 hk[2][16], lk[2][16];
            #pragma unroll
            for (int n=0;n<16;++n){
                float2 b2 = __ldg((const float2*)(bias + 8*n + 2*tig));
                split2(tanh_fast(oc[n][0]+b2.x), tanh_fast(oc[n][1]+b2.y), hk[0][n], lk[0][n]);
                split2(tanh_fast(oc[n][2]+b2.x), tanh_fast(oc[n][3]+b2.y), hk[1][n], lk[1][n]);
            }
            #pragma unroll
            for (int r2=0;r2<2;++r2){
                long base = (grow0 + 8*r2)*64 + 2*tig;
                #pragma unroll
                for (int gk=0;gk<8;++gk){
                    *(u64*)&g_k_hi[base + 8*gk] = ((u64)hk[r2][2*gk+1]<<32) | hk[r2][2*gk];
                    *(u64*)&g_k_lo[base + 8*gk] = ((u64)lk[r2][2*gk+1]<<32) | lk[r2][2*gk];
                }
            }
        } else {
            // V: transpose through smem -> g_vt[b][h][pair-interleaved] (verified in R12)
            __syncthreads();   // all warps done reading ws (about to overwrite)
            float* y_s = (float*)smc;    // [h][row], stride 130
            #pragma unroll
            for (int n=0;n<16;++n){
                float2 b2 = __ldg((const float2*)(bias + 8*n + 2*tig));
                int col = 8*n + 2*tig;
                y_s[(col  )*130 + rowg    ] = tanh_fast(oc[n][0] + b2.x);
                y_s[(col+1)*130 + rowg    ] = tanh_fast(oc[n][1] + b2.y);
                y_s[(col  )*130 + rowg + 8] = tanh_fast(oc[n][2] + b2.x);
                y_s[(col+1)*130 + rowg + 8] = tanh_fast(oc[n][3] + b2.y);
            }
            __syncthreads();
            int h = tid >> 1;
            int phalf = (tid & 1) * 32;
            long gbase = ((long)(b*DM + h))*512 + ((r0 & 1023) >> 1) + phalf;
            #pragma unroll
            for (int g3=0; g3<4; ++g3){
                u32 hp[8], lp[8];
                #pragma unroll
                for (int t=0;t<8;++t){
                    int pg = phalf + g3*8 + t;
                    float2 yy = *(const float2*)(y_s + h*130 + 2*pg);
                    split2(yy.x, yy.y, hp[t], lp[t]);
                }
                // interleaved group order: {0,4,1,5, 2,6,3,7}
                *(uint4*)(g_vt_hi + gbase + g3*8    ) = make_uint4(hp[0],hp[4],hp[1],hp[5]);
                *(uint4*)(g_vt_hi + gbase + g3*8 + 4) = make_uint4(hp[2],hp[6],hp[3],hp[7]);
                *(uint4*)(g_vt_lo + gbase + g3*8    ) = make_uint4(lp[0],lp[4],lp[1],lp[5]);
                *(uint4*)(g_vt_lo + gbase + g3*8 + 4) = make_uint4(lp[2],lp[6],lp[3],lp[7]);
            }
        }
    }
}

// =====================================================================
// Attention (R11 structure verbatim) with LDS.64 B-fragments:
// K stride 72, VT stride 40 (both ≡8 mod 32 -> conflict-free uint2).
// =====================================================================
#define KS_STRIDE 72
#define VT_STRIDE 40
#define MS_STRIDE 68
#define OF_KH 0
#define OF_KL 4608
#define OF_VH 9216
#define OF_VL 14336
#define OF_MS 19456
#define BUF_U32 28160
#define A_SMEM (2*BUF_U32*4)   // 225,280 B

__global__ void __launch_bounds__(256, 1)
attn_kernel(const int* __restrict__ mask, float* __restrict__ out)
{
    extern __shared__ char smc[];
    u32* smp = (u32*)smc;
    u32  sb  = sm_u32(smc);

    int tid = threadIdx.x, wid = tid>>5, lane = tid&31;
    int g = lane>>2, tig = lane&3;
    int b  = blockIdx.y;
    int q0 = blockIdx.x * 128;
    int rowg  = wid*16 + g;
    long grow0 = (long)(b*SEQ + q0 + rowg);

    const uint4* gk_h = (const uint4*)(g_k_hi + (long)(b*SEQ)*64);
    const uint4* gk_l = (const uint4*)(g_k_lo + (long)(b*SEQ)*64);
    const uint4* gv_h = (const uint4*)(g_vt_hi + (long)(b*DM)*512);
    const uint4* gv_l = (const uint4*)(g_vt_lo + (long)(b*DM)*512);
    const int*   mg   = mask + ((long)(b*SEQ + q0))*SEQ;

    // ---- Q fragments (persist): rows rowg, rowg+8 ----
    u32 aqh[2][16], aql[2][16];
    {
        const u32* qh0 = g_q_hi + grow0*64;
        const u32* ql0 = g_q_lo + grow0*64;
        #pragma unroll
        for (int t=0;t<16;++t){
            int c = 4*t + tig;
            aqh[0][t] = __ldg(&qh0[c]);  aqh[1][t] = __ldg(&qh0[8*64 + c]);
            aql[0][t] = __ldg(&ql0[c]);  aql[1][t] = __ldg(&ql0[8*64 + c]);
        }
    }

    auto stage = [&](int jb, int bi){
        u32 base = sb + (u32)(bi*BUF_U32*4);
        int j0 = jb*64;
        #pragma unroll
        for (int p=0;p<4;++p){                 // K: 64 rows x 16 uint4 (hi+lo)
            int i = tid + p*256, row = i>>4, c4 = (i&15)*4;
            int gi = j0*16 + i;
            cp16(base + (OF_KH + row*KS_STRIDE + c4)*4, gk_h + gi);
            cp16(base + (OF_KL + row*KS_STRIDE + c4)*4, gk_l + gi);
        }
        #pragma unroll
        for (int p=0;p<4;++p){                 // V^T: 128 rows x 8 uint4 (hi+lo)
            int i = tid + p*256, row = i>>3, c4 = (i&7)*4;
            int src = row*128 + (j0>>3) + (c4>>2);
            cp16(base + (OF_VH + row*VT_STRIDE + c4)*4, gv_h + src);
            cp16(base + (OF_VL + row*VT_STRIDE + c4)*4, gv_l + src);
        }
        #pragma unroll
        for (int p=0;p<8;++p){                 // mask raw: 128 rows x 16 uint4
            int i = tid + p*256, row = i>>4, c16 = (i&15);
            cp16(base + (OF_MS + row*MS_STRIDE + c16*4)*4,
                 (const uint4*)(mg + (long)row*SEQ + j0) + c16);
        }
    };

    float oc[16][4];
    #pragma unroll
    for (int n=0;n<16;++n){ oc[n][0]=0; oc[n][1]=0; oc[n][2]=0; oc[n][3]=0; }
    float rs0 = 0.0f, rs1 = 0.0f;

    stage(0, 0); CP_COMMIT();

    for (int jb = 0; jb < 16; ++jb) {
        __syncthreads();
        if (jb < 15) { stage(jb+1, (jb+1)&1); CP_COMMIT(); CP_WAIT1(); }
        else         { CP_WAIT0(); }
        __syncthreads();

        u32* bp    = smp + (jb&1)*BUF_U32;
        u32* ks_hi = bp + OF_KH;
        u32* ks_lo = bp + OF_KL;
        u32* vs_hi = bp + OF_VH;
        u32* vs_lo = bp + OF_VL;
        const int* msB = (const int*)(bp + OF_MS);

        // ---- QK: S(16x64 per warp), 3-term split, LDS.64 B-frags ----
        float sc[8][4];
        #pragma unroll
        for (int n=0;n<8;++n){ sc[n][0]=0; sc[n][1]=0; sc[n][2]=0; sc[n][3]=0; }
        #pragma unroll
        for (int n=0;n<8;++n){
            int key = 8*n + g;
            #pragma unroll
            for (int ks=0;ks<8;++ks){
                uint2 bh = *(const uint2*)&ks_hi[key*KS_STRIDE + 8*ks + 2*tig];
                uint2 bl = *(const uint2*)&ks_lo[key*KS_STRIDE + 8*ks + 2*tig];
                mma16816(sc[n], aqh[0][2*ks], aqh[1][2*ks], aqh[0][2*ks+1], aqh[1][2*ks+1], bh.x, bh.y);
                mma16816(sc[n], aqh[0][2*ks], aqh[1][2*ks], aqh[0][2*ks+1], aqh[1][2*ks+1], bl.x, bl.y);
                mma16816(sc[n], aql[0][2*ks], aql[1][2*ks], aql[0][2*ks+1], aql[1][2*ks+1], bh.x, bh.y);
            }
        }

        // ---- mask + exp ----
        const int* mrow0 = msB + rowg*MS_STRIDE;
        const int* mrow1 = mrow0 + 8*MS_STRIDE;
        #pragma unroll
        for (int n=0;n<8;++n){
            int col = 8*n + 2*tig;
            int2 ma  = *(const int2*)(mrow0 + col);
            int2 mb2 = *(const int2*)(mrow1 + col);
            float p0 = ma.x  ? __expf(sc[n][0]) : 0.0f;
            float p1 = ma.y  ? __expf(sc[n][1]) : 0.0f;
            float p2 = mb2.x ? __expf(sc[n][2]) : 0.0f;
            float p3 = mb2.y ? __expf(sc[n][3]) : 0.0f;
            rs0 += p0 + p1;  rs1 += p2 + p3;
            sc[n][0]=p0; sc[n][1]=p1; sc[n][2]=p2; sc[n][3]=p3;
        }

        // ---- PV: O(16x128) += P(16x64) . V^T, LDS.64 B-frags ----
        #pragma unroll
        for (int ks=0;ks<4;++ks){
            u32 ah[4], al[4];
            split2(sc[2*ks  ][0], sc[2*ks  ][1], ah[0], al[0]);
            split2(sc[2*ks  ][2], sc[2*ks  ][3], ah[1], al[1]);
            split2(sc[2*ks+1][0], sc[2*ks+1][1], ah[2], al[2]);
            split2(sc[2*ks+1][2], sc[2*ks+1][3], ah[3], al[3]);
            #pragma unroll
            for (int n=0;n<16;++n){
                int h = 8*n + g;
                uint2 bh = *(const uint2*)&vs_hi[h*VT_STRIDE + 8*ks + 2*tig];
                uint2 bl = *(const uint2*)&vs_lo[h*VT_STRIDE + 8*ks + 2*tig];
                mma16816(oc[n], ah[0],ah[1],ah[2],ah[3], bh.x, bh.y);
                mma16816(oc[n], ah[0],ah[1],ah[2],ah[3], bl.x, bl.y);
                mma16816(oc[n], al[0],al[1],al[2],al[3], bh.x, bh.y);
            }
        }
    }

    // ---- row sums (quad reduce) + normalize + store ----
    rs0 += __shfl_xor_sync(0xFFFFFFFFu, rs0, 1);
    rs0 += __shfl_xor_sync(0xFFFFFFFFu, rs0, 2);
    rs1 += __shfl_xor_sync(0xFFFFFFFFu, rs1, 1);
    rs1 += __shfl_xor_sync(0xFFFFFFFFu, rs1, 2);
    float inv0 = __fdividef(1.0f, rs0);
    float inv1 = __fdividef(1.0f, rs1);

    float* o0 = out + grow0*DM;
    float* o1 = o0 + 8*DM;
    #pragma unroll
    for (int n=0;n<16;++n){
        int col = 8*n + 2*tig;
        *(float2*)(o0 + col) = make_float2(oc[n][0]*inv0, oc[n][1]*inv0);
        *(float2*)(o1 + col) = make_float2(oc[n][2]*inv1, oc[n][3]*inv1);
    }
}

// =====================================================================
extern "C" void kernel_launch(void* const* d_in, const int* in_sizes, int n_in,
                              void* d_out, int out_size)
{
    const float* x    = (const float*)d_in[0];
    const int*   mask = (const int*)  d_in[1];
    const float* Wv   = (const float*)d_in[2];
    const float* bv   = (const float*)d_in[3];
    const float* Wk   = (const float*)d_in[4];
    const float* bk   = (const float*)d_in[5];
    const float* Wq   = (const float*)d_in[6];
    const float* bq   = (const float*)d_in[7];
    float* out = (float*)d_out;

    cudaFuncSetAttribute(proj_tc_kernel, cudaFuncAttributeMaxDynamicSharedMemorySize, P_SMEM_BYTES);
    cudaFuncSetAttribute(attn_kernel,    cudaFuncAttributeMaxDynamicSharedMemorySize, A_SMEM);

    proj_tc_kernel<<<512, 256, P_SMEM_BYTES>>>(x, Wq, bq, Wk, bk, Wv, bv);
    attn_kernel<<<dim3(SEQ/128, BATCH), 256, A_SMEM>>>(mask, out);
}

// round 17
// speedup vs baseline: 2.2031x; 1.3693x over previous
#include <cuda_runtime.h>
#include <cuda_fp16.h>

typedef unsigned int u32;
typedef unsigned short u16;
typedef unsigned long long u64;

#define BATCH 64
#define SEQ   1024
#define DM    128
#define SHIFT 8.0f
#define DEVINL __device__ __forceinline__

// fp16x2 packed pairs as u32.
// Q : [row][4n+tig] hi/lo           (R11 order)
// K : [row][pair-interleaved] hi/lo (R15 order: pos 8g+2t -> pair 8g+t, pos 8g+2t+1 -> pair 8g+4+t)
// VT: [b][h][pair-interleaved]      (single fp16, R15 hi order)
__device__ u32 g_q_hi[BATCH*SEQ*64];
__device__ u32 g_q_lo[BATCH*SEQ*64];
__device__ u32 g_k_hi[BATCH*SEQ*64];
__device__ u32 g_k_lo[BATCH*SEQ*64];
__device__ u32 g_vt  [BATCH*DM*512];   // [b][h][j/2] single fp16

// ---------------- helpers ----------------
DEVINL float tanh_fast(float x){
    float ax = fminf(fabsf(x), 20.0f);
    float e  = __expf(2.0f*ax);
    return copysignf(__fdividef(e-1.0f, e+1.0f), x);
}
DEVINL u32 h2pair(float e0, float e1){ __half2 h = __floats2half2_rn(e0, e1); return *(u32*)&h; }  // low = e0
DEVINL float h2lo_f(u32 p){ __half2 h = *(__half2*)&p; return __low2float(h); }
DEVINL float h2hi_f(u32 p){ __half2 h = *(__half2*)&p; return __high2float(h); }
DEVINL void split2h(float e0, float e1, u32 &hi, u32 &lo){
    hi = h2pair(e0, e1);
    lo = h2pair(e0 - h2lo_f(hi), e1 - h2hi_f(hi));
}
DEVINL void mma16816h(float* c, u32 a0,u32 a1,u32 a2,u32 a3, u32 b0,u32 b1){
    asm volatile("mma.sync.aligned.m16n8k16.row.col.f32.f16.f16.f32 "
        "{%0,%1,%2,%3}, {%4,%5,%6,%7}, {%8,%9}, {%0,%1,%2,%3};"
        : "+f"(c[0]),"+f"(c[1]),"+f"(c[2]),"+f"(c[3])
        : "r"(a0),"r"(a1),"r"(a2),"r"(a3),"r"(b0),"r"(b1));
}
// bf16 kept for the projection GEMM (inputs x ~ N(0,1), W small)
DEVINL u32 bfpair(float e0, float e1){ u32 r; asm("cvt.rn.bf16x2.f32 %0, %1, %2;":"=r"(r):"f"(e1),"f"(e0)); return r; }
DEVINL float bflo_f(u32 p){ return __uint_as_float(p<<16); }
DEVINL float bfhi_f(u32 p){ return __uint_as_float(p & 0xFFFF0000u); }
DEVINL void split2(float e0, float e1, u32 &hi, u32 &lo){
    hi = bfpair(e0, e1);
    lo = bfpair(e0 - bflo_f(hi), e1 - bfhi_f(hi));
}
DEVINL void mma16816(float* c, u32 a0,u32 a1,u32 a2,u32 a3, u32 b0,u32 b1){
    asm volatile("mma.sync.aligned.m16n8k16.row.col.f32.bf16.bf16.f32 "
        "{%0,%1,%2,%3}, {%4,%5,%6,%7}, {%8,%9}, {%0,%1,%2,%3};"
        : "+f"(c[0]),"+f"(c[1]),"+f"(c[2]),"+f"(c[3])
        : "r"(a0),"r"(a1),"r"(a2),"r"(a3),"r"(b0),"r"(b1));
}
DEVINL u32 sm_u32(const void* p){ u32 a; asm("{ .reg .u64 t; cvta.to.shared.u64 t, %1; cvt.u32.u64 %0, t; }":"=r"(a):"l"(p)); return a; }
DEVINL void cp16(u32 dst, const void* src){
    asm volatile("cp.async.cg.shared.global [%0], [%1], 16;"::"r"(dst),"l"(src):"memory");
}
#define CP_COMMIT() asm volatile("cp.async.commit_group;":::"memory")
#define CP_WAIT1()  asm volatile("cp.async.wait_group 1;":::"memory")
#define CP_WAIT0()  asm volatile("cp.async.wait_group 0;":::"memory")

// =====================================================================
// Fused tensorized projections (R15 core; writers emit fp16 layouts)
// =====================================================================
#define PW_STRIDE 68      // u32
#define PW_HI     0
#define PW_LO     8704
#define P_SMEM_BYTES (17408*4)   // 69,632 (y_s transpose scratch: 128*130*4=66,560)

__global__ void __launch_bounds__(256, 1)
proj_tc_kernel(const float* __restrict__ x,
               const float* __restrict__ Wq, const float* __restrict__ bq,
               const float* __restrict__ Wk, const float* __restrict__ bk,
               const float* __restrict__ Wv, const float* __restrict__ bv)
{
    extern __shared__ char smc[];
    u32* ws_hi = (u32*)smc + PW_HI;
    u32* ws_lo = (u32*)smc + PW_LO;

    int tid = threadIdx.x, wid = tid>>5, lane = tid&31;
    int g = lane>>2, tig = lane&3;
    int r0 = blockIdx.x * 128;
    int b  = r0 >> 10;
    int rowg = wid*16 + g;
    long grow0 = (long)(r0 + rowg);

    // ---- x fragments (bf16 hi/lo): rows rowg, rowg+8; persist ----
    u32 axh[2][16], axl[2][16];
    #pragma unroll
    for (int r2=0;r2<2;++r2){
        const float* xr = x + (grow0 + 8*r2)*DM;
        #pragma unroll
        for (int t=0;t<16;++t){
            float2 v = __ldg((const float2*)(xr + 8*t + 2*tig));
            split2(v.x, v.y, axh[r2][t], axl[r2][t]);
        }
    }

    #pragma unroll 1
    for (int sel=0; sel<3; ++sel){
        const float* W    = (sel==0)? Wq : (sel==1)? Wk : Wv;
        const float* bias = (sel==0)? bq : (sel==1)? bk : bv;

        __syncthreads();   // prior sel done reading ws
        #pragma unroll
        for (int p=0;p<16;++p){
            int i = tid + p*256, row = i>>5, c4 = (i&31)*4;
            float4 wv = __ldg((const float4*)(W + (long)row*DM + c4));
            u32 h0,l0,h1,l1;
            split2(wv.x, wv.y, h0, l0);
            split2(wv.z, wv.w, h1, l1);
            *(u64*)(ws_hi + row*PW_STRIDE + (c4>>1)) = ((u64)h1<<32)|h0;
            *(u64*)(ws_lo + row*PW_STRIDE + (c4>>1)) = ((u64)l1<<32)|l0;
        }
        __syncthreads();

        float oc[16][4];
        #pragma unroll
        for (int n=0;n<16;++n){ oc[n][0]=0; oc[n][1]=0; oc[n][2]=0; oc[n][3]=0; }
        #pragma unroll
        for (int n=0;n<16;++n){
            int h = 8*n + g;
            #pragma unroll
            for (int ks=0;ks<8;++ks){
                u32 bh0 = ws_hi[h*PW_STRIDE + 8*ks + tig];
                u32 bh1 = ws_hi[h*PW_STRIDE + 8*ks + 4 + tig];
                u32 bl0 = ws_lo[h*PW_STRIDE + 8*ks + tig];
                u32 bl1 = ws_lo[h*PW_STRIDE + 8*ks + 4 + tig];
                mma16816(oc[n], axh[0][2*ks], axh[1][2*ks], axh[0][2*ks+1], axh[1][2*ks+1], bh0, bh1);
                mma16816(oc[n], axh[0][2*ks], axh[1][2*ks], axh[0][2*ks+1], axh[1][2*ks+1], bl0, bl1);
                mma16816(oc[n], axl[0][2*ks], axl[1][2*ks], axl[0][2*ks+1], axl[1][2*ks+1], bh0, bh1);
            }
        }

        if (sel == 0){
            // Q fp16 hi/lo (R11 order): pair p=4n+tig at col 4n+tig
            #pragma unroll
            for (int n=0;n<16;++n){
                float2 b2 = __ldg((const float2*)(bias + 8*n + 2*tig));
                float y0 = tanh_fast(oc[n][0] + b2.x);
                float y1 = tanh_fast(oc[n][1] + b2.y);
                float y2 = tanh_fast(oc[n][2] + b2.x);
                float y3 = tanh_fast(oc[n][3] + b2.y);
                u32 h2,l2;
                split2h(y0,y1,h2,l2);
                g_q_hi[grow0*64 + 4*n + tig] = h2;  g_q_lo[grow0*64 + 4*n + tig] = l2;
                split2h(y2,y3,h2,l2);
                g_q_hi[(grow0+8)*64 + 4*n + tig] = h2;  g_q_lo[(grow0+8)*64 + 4*n + tig] = l2;
            }
        } else if (sel == 1){
            // K fp16 hi/lo, pair-interleaved (R15 layout)
            u32 hk[2][16], lk[2][16];
            #pragma unroll
            for (int n=0;n<16;++n){
                float2 b2 = __ldg((const float2*)(bias + 8*n + 2*tig));
                split2h(tanh_fast(oc[n][0]+b2.x), tanh_fast(oc[n][1]+b2.y), hk[0][n], lk[0][n]);
                split2h(tanh_fast(oc[n][2]+b2.x), tanh_fast(oc[n][3]+b2.y), hk[1][n], lk[1][n]);
            }
            #pragma unroll
            for (int r2=0;r2<2;++r2){
                long base = (grow0 + 8*r2)*64 + 2*tig;
                #pragma unroll
                for (int gk=0;gk<8;++gk){
                    *(u64*)&g_k_hi[base + 8*gk] = ((u64)hk[r2][2*gk+1]<<32) | hk[r2][2*gk];
                    *(u64*)&g_k_lo[base + 8*gk] = ((u64)lk[r2][2*gk+1]<<32) | lk[r2][2*gk];
                }
            }
        } else {
            // V: transpose through smem -> g_vt[b][h][pair-interleaved], SINGLE fp16
            __syncthreads();   // all warps done reading ws (about to overwrite)
            float* y_s = (float*)smc;    // [h][row], stride 130
            #pragma unroll
            for (int n=0;n<16;++n){
                float2 b2 = __ldg((const float2*)(bias + 8*n + 2*tig));
                int col = 8*n + 2*tig;
                y_s[(col  )*130 + rowg    ] = tanh_fast(oc[n][0] + b2.x);
                y_s[(col+1)*130 + rowg    ] = tanh_fast(oc[n][1] + b2.y);
                y_s[(col  )*130 + rowg + 8] = tanh_fast(oc[n][2] + b2.x);
                y_s[(col+1)*130 + rowg + 8] = tanh_fast(oc[n][3] + b2.y);
            }
            __syncthreads();
            int h = tid >> 1;
            int phalf = (tid & 1) * 32;
            long gbase = ((long)(b*DM + h))*512 + ((r0 & 1023) >> 1) + phalf;
            #pragma unroll
            for (int g3=0; g3<4; ++g3){
                u32 hp[8];
                #pragma unroll
                for (int t=0;t<8;++t){
                    int pg = phalf + g3*8 + t;
                    float2 yy = *(const float2*)(y_s + h*130 + 2*pg);
                    hp[t] = h2pair(yy.x, yy.y);
                }
                // interleaved group order: {0,4,1,5, 2,6,3,7}
                *(uint4*)(g_vt + gbase + g3*8    ) = make_uint4(hp[0],hp[4],hp[1],hp[5]);
                *(uint4*)(g_vt + gbase + g3*8 + 4) = make_uint4(hp[2],hp[6],hp[3],hp[7]);
            }
        }
    }
}

// =====================================================================
// Attention (R15 structure): fp16 3-term QK, SINGLE-term fp16 PV.
// =====================================================================
#define KS_STRIDE 72
#define VT_STRIDE 40
#define MS_STRIDE 68
#define OF_KH 0
#define OF_KL 4608
#define OF_VH 9216
#define OF_MS 14336
#define BUF_U32 23040
#define A_SMEM (2*BUF_U32*4)   // 184,320 B

__global__ void __launch_bounds__(256, 1)
attn_kernel(const int* __restrict__ mask, float* __restrict__ out)
{
    extern __shared__ char smc[];
    u32* smp = (u32*)smc;
    u32  sb  = sm_u32(smc);

    int tid = threadIdx.x, wid = tid>>5, lane = tid&31;
    int g = lane>>2, tig = lane&3;
    int b  = blockIdx.y;
    int q0 = blockIdx.x * 128;
    int rowg  = wid*16 + g;
    long grow0 = (long)(b*SEQ + q0 + rowg);

    const uint4* gk_h = (const uint4*)(g_k_hi + (long)(b*SEQ)*64);
    const uint4* gk_l = (const uint4*)(g_k_lo + (long)(b*SEQ)*64);
    const uint4* gv   = (const uint4*)(g_vt   + (long)(b*DM)*512);
    const int*   mg   = mask + ((long)(b*SEQ + q0))*SEQ;

    // ---- Q fragments (persist): rows rowg, rowg+8 ----
    u32 aqh[2][16], aql[2][16];
    {
        const u32* qh0 = g_q_hi + grow0*64;
        const u32* ql0 = g_q_lo + grow0*64;
        #pragma unroll
        for (int t=0;t<16;++t){
            int c = 4*t + tig;
            aqh[0][t] = __ldg(&qh0[c]);  aqh[1][t] = __ldg(&qh0[8*64 + c]);
            aql[0][t] = __ldg(&ql0[c]);  aql[1][t] = __ldg(&ql0[8*64 + c]);
        }
    }

    auto stage = [&](int jb, int bi){
        u32 base = sb + (u32)(bi*BUF_U32*4);
        int j0 = jb*64;
        #pragma unroll
        for (int p=0;p<4;++p){                 // K: 64 rows x 16 uint4 (hi+lo)
            int i = tid + p*256, row = i>>4, c4 = (i&15)*4;
            int gi = j0*16 + i;
            cp16(base + (OF_KH + row*KS_STRIDE + c4)*4, gk_h + gi);
            cp16(base + (OF_KL + row*KS_STRIDE + c4)*4, gk_l + gi);
        }
        #pragma unroll
        for (int p=0;p<4;++p){                 // V^T: 128 rows x 8 uint4 (single fp16)
            int i = tid + p*256, row = i>>3, c4 = (i&7)*4;
            int src = row*128 + (j0>>3) + (c4>>2);
            cp16(base + (OF_VH + row*VT_STRIDE + c4)*4, gv + src);
        }
        #pragma unroll
        for (int p=0;p<8;++p){                 // mask raw: 128 rows x 16 uint4
            int i = tid + p*256, row = i>>4, c16 = (i&15);
            cp16(base + (OF_MS + row*MS_STRIDE + c16*4)*4,
                 (const uint4*)(mg + (long)row*SEQ + j0) + c16);
        }
    };

    float oc[16][4];
    #pragma unroll
    for (int n=0;n<16;++n){ oc[n][0]=0; oc[n][1]=0; oc[n][2]=0; oc[n][3]=0; }
    float rs0 = 0.0f, rs1 = 0.0f;

    stage(0, 0); CP_COMMIT();

    for (int jb = 0; jb < 16; ++jb) {
        __syncthreads();
        if (jb < 15) { stage(jb+1, (jb+1)&1); CP_COMMIT(); CP_WAIT1(); }
        else         { CP_WAIT0(); }
        __syncthreads();

        u32* bp    = smp + (jb&1)*BUF_U32;
        u32* ks_hi = bp + OF_KH;
        u32* ks_lo = bp + OF_KL;
        u32* vs_h  = bp + OF_VH;
        const int* msB = (const int*)(bp + OF_MS);

        // ---- QK: S(16x64 per warp), fp16 3-term, LDS.64 B-frags ----
        float sc[8][4];
        #pragma unroll
        for (int n=0;n<8;++n){ sc[n][0]=0; sc[n][1]=0; sc[n][2]=0; sc[n][3]=0; }
        #pragma unroll
        for (int n=0;n<8;++n){
            int key = 8*n + g;
            #pragma unroll
            for (int ks=0;ks<8;++ks){
                uint2 bh = *(const uint2*)&ks_hi[key*KS_STRIDE + 8*ks + 2*tig];
                uint2 bl = *(const uint2*)&ks_lo[key*KS_STRIDE + 8*ks + 2*tig];
                mma16816h(sc[n], aqh[0][2*ks], aqh[1][2*ks], aqh[0][2*ks+1], aqh[1][2*ks+1], bh.x, bh.y);
                mma16816h(sc[n], aqh[0][2*ks], aqh[1][2*ks], aqh[0][2*ks+1], aqh[1][2*ks+1], bl.x, bl.y);
                mma16816h(sc[n], aql[0][2*ks], aql[1][2*ks], aql[0][2*ks+1], aql[1][2*ks+1], bh.x, bh.y);
            }
        }

        // ---- mask + exp(s - SHIFT) -> fp16 P packs; rowsum from ROUNDED P ----
        u32 aph[8], apl[8];
        const int* mrow0 = msB + rowg*MS_STRIDE;
        const int* mrow1 = mrow0 + 8*MS_STRIDE;
        #pragma unroll
        for (int n=0;n<8;++n){
            int col = 8*n + 2*tig;
            int2 ma  = *(const int2*)(mrow0 + col);
            int2 mb2 = *(const int2*)(mrow1 + col);
            float p0 = ma.x  ? __expf(sc[n][0] - SHIFT) : 0.0f;
            float p1 = ma.y  ? __expf(sc[n][1] - SHIFT) : 0.0f;
            float p2 = mb2.x ? __expf(sc[n][2] - SHIFT) : 0.0f;
            float p3 = mb2.y ? __expf(sc[n][3] - SHIFT) : 0.0f;
            u32 h01 = h2pair(p0, p1);
            u32 h23 = h2pair(p2, p3);
            aph[n] = h01;  apl[n] = h23;
            rs0 += h2lo_f(h01) + h2hi_f(h01);
            rs1 += h2lo_f(h23) + h2hi_f(h23);
        }

        // ---- PV: O(16x128) += P(16x64) . V^T, SINGLE fp16 term ----
        #pragma unroll
        for (int ks=0;ks<4;++ks){
            u32 a0 = aph[2*ks], a1 = apl[2*ks], a2 = aph[2*ks+1], a3 = apl[2*ks+1];
            #pragma unroll
            for (int n=0;n<16;++n){
                int h = 8*n + g;
                uint2 bh = *(const uint2*)&vs_h[h*VT_STRIDE + 8*ks + 2*tig];
                mma16816h(oc[n], a0, a1, a2, a3, bh.x, bh.y);
            }
        }
    }

    // ---- row sums (quad reduce) + normalize + store ----
    rs0 += __shfl_xor_sync(0xFFFFFFFFu, rs0, 1);
    rs0 += __shfl_xor_sync(0xFFFFFFFFu, rs0, 2);
    rs1 += __shfl_xor_sync(0xFFFFFFFFu, rs1, 1);
    rs1 += __shfl_xor_sync(0xFFFFFFFFu, rs1, 2);
    float inv0 = __fdividef(1.0f, rs0);
    float inv1 = __fdividef(1.0f, rs1);

    float* o0 = out + grow0*DM;
    float* o1 = o0 + 8*DM;
    #pragma unroll
    for (int n=0;n<16;++n){
        int col = 8*n + 2*tig;
        *(float2*)(o0 + col) = make_float2(oc[n][0]*inv0, oc[n][1]*inv0);
        *(float2*)(o1 + col) = make_float2(oc[n][2]*inv1, oc[n][3]*inv1);
    }
}

// =====================================================================
extern "C" void kernel_launch(void* const* d_in, const int* in_sizes, int n_in,
                              void* d_out, int out_size)
{
    const float* x    = (const float*)d_in[0];
    const int*   mask = (const int*)  d_in[1];
    const float* Wv   = (const float*)d_in[2];
    const float* bv   = (const float*)d_in[3];
    const float* Wk   = (const float*)d_in[4];
    const float* bk   = (const float*)d_in[5];
    const float* Wq   = (const float*)d_in[6];
    const float* bq   = (const float*)d_in[7];
    float* out = (float*)d_out;

    cudaFuncSetAttribute(proj_tc_kernel, cudaFuncAttributeMaxDynamicSharedMemorySize, P_SMEM_BYTES);
    cudaFuncSetAttribute(attn_kernel,    cudaFuncAttributeMaxDynamicSharedMemorySize, A_SMEM);

    proj_tc_kernel<<<512, 256, P_SMEM_BYTES>>>(x, Wq, bq, Wk, bk, Wv, bv);
    attn_kernel<<<dim3(SEQ/128, BATCH), 256, A_SMEM>>>(mask, out);
}